// round 14
// baseline (speedup 1.0000x reference)
#include <cuda_runtime.h>
#include <cuda_fp16.h>
#include <cstdint>

#define EPSILON_F 1e-9f
#define NQ 100
#define L_SEQ 512
#define THREADS 768               // 24 warps; reg ceiling 80/thr
#define ROW_BYTES 2048            // 512 x int32
#define PAIR_BYTES 4096

// fp16 copy of eta, produced once per launch by convert_kernel
__device__ __align__(16) __half g_eta_h[131072];

__device__ __forceinline__ uint32_t smem_u32(const void* p) {
    uint32_t a;
    asm("{ .reg .u64 t; cvta.to.shared.u64 t, %1; cvt.u32.u64 %0, t; }"
        : "=r"(a) : "l"(p));
    return a;
}
__device__ __forceinline__ void mbar_init(uint32_t m, uint32_t cnt) {
    asm volatile("mbarrier.init.shared.b64 [%0], %1;" :: "r"(m), "r"(cnt) : "memory");
}
__device__ __forceinline__ void mbar_expect_tx(uint32_t m, uint32_t bytes) {
    asm volatile("mbarrier.arrive.expect_tx.shared.b64 _, [%0], %1;"
                 :: "r"(m), "r"(bytes) : "memory");
}
__device__ __forceinline__ void mbar_wait(uint32_t m, uint32_t parity) {
    asm volatile(
        "{\n\t.reg .pred P;\n\t"
        "LW_%=:\n\t"
        "mbarrier.try_wait.parity.acquire.cta.shared::cta.b64 P, [%0], %1, 0x989680;\n\t"
        "@P bra LD_%=;\n\t"
        "bra LW_%=;\n\t"
        "LD_%=:\n\t}"
        :: "r"(m), "r"(parity) : "memory");
}
__device__ __forceinline__ void bulk_g2s(uint32_t dst, const void* src,
                                         uint32_t bytes, uint32_t mbar) {
    asm volatile(
        "cp.async.bulk.shared::cluster.global.mbarrier::complete_tx::bytes "
        "[%0], [%1], %2, [%3];"
        :: "r"(dst), "l"(src), "r"(bytes), "r"(mbar) : "memory");
}

__global__ void convert_kernel(const float* __restrict__ eta, int V) {
    const int n2 = V >> 1;
    const float2* e2 = reinterpret_cast<const float2*>(eta);
    __half2* d2 = reinterpret_cast<__half2*>(g_eta_h);
    const int i = blockIdx.x * blockDim.x + threadIdx.x;
    if (i < n2) {
        float2 v = __ldg(e2 + i);
        d2[i] = __floats2half2_rn(v.x, v.y);
    }
    if (i == 0 && (V & 1))
        g_eta_h[V - 1] = __float2half_rn(__ldg(eta + V - 1));
}

// Persistent: 1 CTA/SM, 24 warps. fp16 table via one cp.async.bulk.
// Dual-row stages: lanes 0-15 own row 2p, lanes 16-31 own row 2p+1.
// 4 SHFLs reduce BOTH rows; per-row loop/store overhead halved.
// Depth-2 stage ring = 4 rows in flight per warp.
__global__ __launch_bounds__(THREADS, 1)
void gather_kernel(const int* __restrict__ idx,
                   const float* __restrict__ t_ptr,
                   float* __restrict__ out, int B, int V) {
    extern __shared__ __align__(16) unsigned char smem[];

    const uint32_t TBL = (uint32_t)((2 * V + 15) & ~15);
    __half* tbl = reinterpret_cast<__half*>(smem);
    float*  ws  = reinterpret_cast<float*>(smem + TBL);

    const uint32_t sbase = smem_u32(smem);
    const uint32_t m_tbl = sbase + TBL + 64;

    const int tid   = threadIdx.x;
    const int warp  = tid >> 5;
    const int lane  = tid & 31;
    const int half  = lane >> 4;                  // 0: row 2p, 1: row 2p+1
    const int hl    = lane & 15;
    const int warps = blockDim.x >> 5;            // 24
    const int pstride = gridDim.x * warps;        // pair stride

    const float t = __ldg(t_ptr);
    const char* ibase = reinterpret_cast<const char*>(idx);

    if (tid == 0) mbar_init(m_tbl, 1);

    const int npairs = B >> 1;
    int p = blockIdx.x * warps + warp;

    // lane-local byte offset within a pair block
    const uint32_t loff = (uint32_t)half * ROW_BYTES + (uint32_t)hl * 16;

    // ---- prologue: issue 2 stages' index loads EARLY (hidden by staging) ----
    int4 bufA[8], bufB[8];
    if (p < npairs) {
        const char* pa = ibase + (uint32_t)p * PAIR_BYTES + loff;
        #pragma unroll
        for (int j = 0; j < 8; j++)
            bufA[j] = __ldcs(reinterpret_cast<const int4*>(pa + j * 256));
    }
    if (p + pstride < npairs) {
        const char* pb = ibase + (uint32_t)(p + pstride) * PAIR_BYTES + loff;
        #pragma unroll
        for (int j = 0; j < 8; j++)
            bufB[j] = __ldcs(reinterpret_cast<const int4*>(pb + j * 256));
    }

    // ---- scalar part: trapz(exp(-E),E), warps 0-3 ----
    if (tid < 128) {
        float val = 0.0f;
        if (tid < NQ - 1) {
            float Ei = ((float)tid       * (1.0f / (NQ - 1))) * t;
            float Ej = ((float)(tid + 1) * (1.0f / (NQ - 1))) * t;
            val = 0.5f * (__expf(-Ei) + __expf(-Ej)) * (Ej - Ei);
        }
        #pragma unroll
        for (int off = 16; off; off >>= 1)
            val += __shfl_xor_sync(0xffffffffu, val, off);
        if ((tid & 31) == 0) ws[tid >> 5] = val;
    }
    __syncthreads();                               // mbar init + ws visible

    // ---- one bulk copy brings the whole fp16 table into smem ----
    if (tid == 0) {
        mbar_expect_tx(m_tbl, TBL);
        bulk_g2s(sbase, g_eta_h, TBL, m_tbl);
    }

    const float base = (ws[0] + ws[1] + ws[2] + ws[3])
                     - 0.5f * t * logf(t + EPSILON_F);

    mbar_wait(m_tbl, 0);                           // table ready

    if (p < npairs) {
        // stage: gather BUF's pair, refill BUF from pair p+2*pstride,
        // reduce both rows with 4 SHFLs, store via lanes 0 and 16
        #define STAGE(BUF)                                                    \
        {                                                                     \
            float a = 0.0f, b = 0.0f;                                         \
            _Pragma("unroll")                                                 \
            for (int j = 0; j < 8; j++) {                                     \
                a += __half2float(tbl[BUF[j].x]);                             \
                b += __half2float(tbl[BUF[j].y]);                             \
                a += __half2float(tbl[BUF[j].z]);                             \
                b += __half2float(tbl[BUF[j].w]);                             \
            }                                                                 \
            const int rp = p + 2 * pstride;                                   \
            if (rp < npairs) {                                                \
                const char* pr = ibase + (uint32_t)rp * PAIR_BYTES + loff;    \
                _Pragma("unroll")                                             \
                for (int j = 0; j < 8; j++)                                   \
                    BUF[j] = __ldcs(                                          \
                        reinterpret_cast<const int4*>(pr + j * 256));         \
            }                                                                 \
            float s = a + b;                                                  \
            _Pragma("unroll")                                                 \
            for (int off = 8; off; off >>= 1)                                 \
                s += __shfl_xor_sync(0xffffffffu, s, off);                    \
            if (hl == 0) out[2 * p + half] = s + base;                        \
        }

        for (;;) {
            STAGE(bufA); p += pstride; if (p >= npairs) break;
            STAGE(bufB); p += pstride; if (p >= npairs) break;
        }
        #undef STAGE
    }

    // odd-B tail: one leftover row handled by block 0, warp 0 (full warp)
    if ((B & 1) && blockIdx.x == 0 && warp == 0) {
        const int row = B - 1;
        const int4* pr = reinterpret_cast<const int4*>(
            ibase + (size_t)row * ROW_BYTES);
        float s = 0.0f;
        #pragma unroll
        for (int j = 0; j < 4; j++) {
            int4 u = __ldcs(&pr[j * 32 + lane]);
            s += __half2float(tbl[u.x]) + __half2float(tbl[u.y])
               + __half2float(tbl[u.z]) + __half2float(tbl[u.w]);
        }
        #pragma unroll
        for (int off = 16; off; off >>= 1)
            s += __shfl_xor_sync(0xffffffffu, s, off);
        if (lane == 0) out[row] = s + base;
    }
}

extern "C" void kernel_launch(void* const* d_in, const int* in_sizes, int n_in,
                              void* d_out, int out_size) {
    const int*   idx = (const int*)d_in[0];     // [B, 512] int32
    const float* eta = (const float*)d_in[1];   // [V] f32
    const float* t   = (const float*)d_in[2];   // scalar f32
    float* out = (float*)d_out;

    const int B = in_sizes[0] / L_SEQ;
    const int V = in_sizes[1];

    // one-wave convert: ceil((V/2)/256) blocks
    const int cb = ((V >> 1) + 255) / 256;
    convert_kernel<<<cb, 256>>>(eta, V);

    int dev = 0, sms = 148;
    cudaGetDevice(&dev);
    cudaDeviceGetAttribute(&sms, cudaDevAttrMultiProcessorCount, dev);

    const size_t TBL = (size_t)((2 * V + 15) & ~15);
    const size_t smem = TBL + 64 + 64;           // table + ws + mbar
    cudaFuncSetAttribute(gather_kernel,
                         cudaFuncAttributeMaxDynamicSharedMemorySize, (int)smem);

    gather_kernel<<<sms, THREADS, smem>>>(idx, t, out, B, V);
}

// round 15
// speedup vs baseline: 1.1836x; 1.1836x over previous
#include <cuda_runtime.h>
#include <cuda_fp16.h>
#include <cstdint>

#define EPSILON_F 1e-9f
#define NQ 100
#define L_SEQ 512
#define THREADS 1024              // 32 warps; reg ceiling 64/thr
#define DEPTH 2
#define PF_DIST 8                 // prefetch-to-L2 distance (rows per warp)
#define ROW_BYTES 2048

// fp16 copy of eta, produced once per launch by convert_kernel
__device__ __align__(16) __half g_eta_h[131072];

__device__ __forceinline__ uint32_t smem_u32(const void* p) {
    uint32_t a;
    asm("{ .reg .u64 t; cvta.to.shared.u64 t, %1; cvt.u32.u64 %0, t; }"
        : "=r"(a) : "l"(p));
    return a;
}
__device__ __forceinline__ void mbar_init(uint32_t m, uint32_t cnt) {
    asm volatile("mbarrier.init.shared.b64 [%0], %1;" :: "r"(m), "r"(cnt) : "memory");
}
__device__ __forceinline__ void mbar_expect_tx(uint32_t m, uint32_t bytes) {
    asm volatile("mbarrier.arrive.expect_tx.shared.b64 _, [%0], %1;"
                 :: "r"(m), "r"(bytes) : "memory");
}
__device__ __forceinline__ void mbar_wait(uint32_t m, uint32_t parity) {
    asm volatile(
        "{\n\t.reg .pred P;\n\t"
        "LW_%=:\n\t"
        "mbarrier.try_wait.parity.acquire.cta.shared::cta.b64 P, [%0], %1, 0x989680;\n\t"
        "@P bra LD_%=;\n\t"
        "bra LW_%=;\n\t"
        "LD_%=:\n\t}"
        :: "r"(m), "r"(parity) : "memory");
}
__device__ __forceinline__ void bulk_g2s(uint32_t dst, const void* src,
                                         uint32_t bytes, uint32_t mbar) {
    asm volatile(
        "cp.async.bulk.shared::cluster.global.mbarrier::complete_tx::bytes "
        "[%0], [%1], %2, [%3];"
        :: "r"(dst), "l"(src), "r"(bytes), "r"(mbar) : "memory");
}

__global__ void convert_kernel(const float* __restrict__ eta, int V) {
    const int n2 = V >> 1;
    const float2* e2 = reinterpret_cast<const float2*>(eta);
    __half2* d2 = reinterpret_cast<__half2*>(g_eta_h);
    const int i = blockIdx.x * blockDim.x + threadIdx.x;
    if (i < n2) {
        float2 v = __ldg(e2 + i);
        d2[i] = __floats2half2_rn(v.x, v.y);
    }
    if (i == 0 && (V & 1))
        g_eta_h[V - 1] = __float2half_rn(__ldg(eta + V - 1));
}

// Persistent: 1 CTA/SM, 32 warps, depth-2 register ring + L2 prefetch
// (refills hit L2 ~250cyc < depth-2 coverage). Pointer-increment addressing
// keeps ALU off the critical path. fp16 table via one cp.async.bulk.
__global__ __launch_bounds__(THREADS, 1)
void gather_kernel(const int* __restrict__ idx,
                   const float* __restrict__ t_ptr,
                   float* __restrict__ out, int B, int V) {
    extern __shared__ __align__(16) unsigned char smem[];

    const uint32_t TBL = (uint32_t)((2 * V + 15) & ~15);
    __half* tbl = reinterpret_cast<__half*>(smem);
    float*  ws  = reinterpret_cast<float*>(smem + TBL);

    const uint32_t sbase = smem_u32(smem);
    const uint32_t m_tbl = sbase + TBL + 64;

    const int tid    = threadIdx.x;
    const int warp   = tid >> 5;
    const int lane   = tid & 31;
    const int warps  = blockDim.x >> 5;           // 32
    const int stride = gridDim.x * warps;

    const float t = __ldg(t_ptr);
    const char* ibase = reinterpret_cast<const char*>(idx);

    if (tid == 0) mbar_init(m_tbl, 1);

    const int row0 = blockIdx.x * warps + warp;
    const long step_bytes = (long)stride * ROW_BYTES;

    // ---- prologue: issue DEPTH rows' index loads EARLY ----
    int4 buf0[4], buf1[4];
    if (row0 < B) {
        const int4* p = reinterpret_cast<const int4*>(
            ibase + (size_t)row0 * ROW_BYTES);
        #pragma unroll
        for (int j = 0; j < 4; j++) buf0[j] = __ldcs(&p[j * 32 + lane]);
    }
    if (row0 + stride < B) {
        const int4* p = reinterpret_cast<const int4*>(
            ibase + (size_t)(row0 + stride) * ROW_BYTES);
        #pragma unroll
        for (int j = 0; j < 4; j++) buf1[j] = __ldcs(&p[j * 32 + lane]);
    }

    // prefetch rows DEPTH..PF_DIST-1 to L2 (lead for the first refills)
    for (int k = DEPTH; k < PF_DIST; k++) {
        const long r = (long)row0 + (long)k * stride;
        if (r < B) {
            const char* pp = ibase + r * ROW_BYTES + (lane << 6);
            asm volatile("prefetch.global.L2 [%0];" :: "l"(pp));
        }
    }

    // ---- scalar part: trapz(exp(-E),E), warps 0-3 ----
    if (tid < 128) {
        float val = 0.0f;
        if (tid < NQ - 1) {
            float Ei = ((float)tid       * (1.0f / (NQ - 1))) * t;
            float Ej = ((float)(tid + 1) * (1.0f / (NQ - 1))) * t;
            val = 0.5f * (__expf(-Ei) + __expf(-Ej)) * (Ej - Ei);
        }
        #pragma unroll
        for (int off = 16; off; off >>= 1)
            val += __shfl_xor_sync(0xffffffffu, val, off);
        if (lane == 0) ws[warp] = val;
    }
    __syncthreads();                               // mbar init + ws visible

    // ---- one bulk copy brings the whole fp16 table into smem ----
    if (tid == 0) {
        mbar_expect_tx(m_tbl, TBL);
        bulk_g2s(sbase, g_eta_h, TBL, m_tbl);
    }

    const float base = (ws[0] + ws[1] + ws[2] + ws[3])
                     - 0.5f * t * logf(t + EPSILON_F);

    mbar_wait(m_tbl, 0);                           // table ready

    if (row0 >= B) return;
    int row = row0;

    // pointer-increment state (one IADD each per stage)
    const char* re_ptr = ibase + ((long)row0 + (long)DEPTH * stride) * ROW_BYTES
                       + ((uint32_t)lane << 4);
    const char* pf_ptr = ibase + ((long)row0 + (long)PF_DIST * stride) * ROW_BYTES
                       + ((uint32_t)lane << 6);

    // stage: prefetch row+PF (L2), gather BUF's row, refill BUF (L2 hit)
    #define STAGE(BUF)                                                        \
    {                                                                         \
        if (row + PF_DIST * stride < B)                                       \
            asm volatile("prefetch.global.L2 [%0];" :: "l"(pf_ptr));          \
        float a = 0.0f, b = 0.0f, c = 0.0f, d = 0.0f;                         \
        _Pragma("unroll")                                                     \
        for (int j = 0; j < 4; j++) {                                         \
            a += __half2float(tbl[BUF[j].x]);                                 \
            b += __half2float(tbl[BUF[j].y]);                                 \
            c += __half2float(tbl[BUF[j].z]);                                 \
            d += __half2float(tbl[BUF[j].w]);                                 \
        }                                                                     \
        if (row + DEPTH * stride < B) {                                       \
            _Pragma("unroll")                                                 \
            for (int j = 0; j < 4; j++)                                       \
                BUF[j] = __ldcs(reinterpret_cast<const int4*>(                \
                    re_ptr + j * 512));                                       \
        }                                                                     \
        re_ptr += step_bytes;                                                 \
        pf_ptr += step_bytes;                                                 \
        float s = (a + b) + (c + d);                                          \
        _Pragma("unroll")                                                     \
        for (int off = 16; off; off >>= 1)                                    \
            s += __shfl_xor_sync(0xffffffffu, s, off);                        \
        if (lane == 0) out[row] = s + base;                                   \
    }

    for (;;) {
        STAGE(buf0); row += stride; if (row >= B) break;
        STAGE(buf1); row += stride; if (row >= B) break;
    }
    #undef STAGE
}

extern "C" void kernel_launch(void* const* d_in, const int* in_sizes, int n_in,
                              void* d_out, int out_size) {
    const int*   idx = (const int*)d_in[0];     // [B, 512] int32
    const float* eta = (const float*)d_in[1];   // [V] f32
    const float* t   = (const float*)d_in[2];   // scalar f32
    float* out = (float*)d_out;

    const int B = in_sizes[0] / L_SEQ;
    const int V = in_sizes[1];

    // one-wave convert: ceil((V/2)/256) blocks
    const int cb = ((V >> 1) + 255) / 256;
    convert_kernel<<<cb, 256>>>(eta, V);

    int dev = 0, sms = 148;
    cudaGetDevice(&dev);
    cudaDeviceGetAttribute(&sms, cudaDevAttrMultiProcessorCount, dev);

    const size_t TBL = (size_t)((2 * V + 15) & ~15);
    const size_t smem = TBL + 64 + 64;           // table + ws + mbar
    cudaFuncSetAttribute(gather_kernel,
                         cudaFuncAttributeMaxDynamicSharedMemorySize, (int)smem);

    gather_kernel<<<sms, THREADS, smem>>>(idx, t, out, B, V);
}

// round 16
// speedup vs baseline: 1.1860x; 1.0020x over previous
#include <cuda_runtime.h>
#include <cuda_fp16.h>
#include <cstdint>

#define EPSILON_F 1e-9f
#define NQ 100
#define L_SEQ 512
#define THREADS 768               // 24 warps; reg ceiling 84/thr
#define DEPTH 3
#define PF_DIST 8                 // prefetch-to-L2 distance (rows, per warp)

// fp16 copy of eta, produced once per launch by convert_kernel
__device__ __align__(16) __half g_eta_h[131072];

__device__ __forceinline__ uint32_t smem_u32(const void* p) {
    uint32_t a;
    asm("{ .reg .u64 t; cvta.to.shared.u64 t, %1; cvt.u32.u64 %0, t; }"
        : "=r"(a) : "l"(p));
    return a;
}
__device__ __forceinline__ void mbar_init(uint32_t m, uint32_t cnt) {
    asm volatile("mbarrier.init.shared.b64 [%0], %1;" :: "r"(m), "r"(cnt) : "memory");
}
__device__ __forceinline__ void mbar_expect_tx(uint32_t m, uint32_t bytes) {
    asm volatile("mbarrier.arrive.expect_tx.shared.b64 _, [%0], %1;"
                 :: "r"(m), "r"(bytes) : "memory");
}
__device__ __forceinline__ void mbar_wait(uint32_t m, uint32_t parity) {
    asm volatile(
        "{\n\t.reg .pred P;\n\t"
        "LW_%=:\n\t"
        "mbarrier.try_wait.parity.acquire.cta.shared::cta.b64 P, [%0], %1, 0x989680;\n\t"
        "@P bra LD_%=;\n\t"
        "bra LW_%=;\n\t"
        "LD_%=:\n\t}"
        :: "r"(m), "r"(parity) : "memory");
}
__device__ __forceinline__ void bulk_g2s(uint32_t dst, const void* src,
                                         uint32_t bytes, uint32_t mbar) {
    asm volatile(
        "cp.async.bulk.shared::cluster.global.mbarrier::complete_tx::bytes "
        "[%0], [%1], %2, [%3];"
        :: "r"(dst), "l"(src), "r"(bytes), "r"(mbar) : "memory");
}

__global__ void convert_kernel(const float* __restrict__ eta, int V) {
    const int n2 = V >> 1;
    const float2* e2 = reinterpret_cast<const float2*>(eta);
    __half2* d2 = reinterpret_cast<__half2*>(g_eta_h);
    const int i = blockIdx.x * blockDim.x + threadIdx.x;
    if (i < n2) {
        float2 v = __ldg(e2 + i);
        d2[i] = __floats2half2_rn(v.x, v.y);
    }
    if (i == 0 && (V & 1))
        g_eta_h[V - 1] = __float2half_rn(__ldg(eta + V - 1));
}

// Persistent: 1 CTA/SM, 24 warps, depth-3 register ring, fp16 table via one
// cp.async.bulk, L2 prefetch 8 rows ahead. NEW: one-time per-warp nanosleep
// stagger after table-ready to break the chip-wide gather/refill convoy
// (all warps otherwise start phase-aligned and alternate in lockstep,
// leaving both crossbar and DRAM at ~50% duty).
__global__ __launch_bounds__(THREADS, 1)
void gather_kernel(const int* __restrict__ idx,
                   const float* __restrict__ t_ptr,
                   float* __restrict__ out, int B, int V) {
    extern __shared__ __align__(16) unsigned char smem[];

    const uint32_t TBL = (uint32_t)((2 * V + 15) & ~15);
    __half* tbl = reinterpret_cast<__half*>(smem);
    float*  ws  = reinterpret_cast<float*>(smem + TBL);

    const uint32_t sbase = smem_u32(smem);
    const uint32_t m_tbl = sbase + TBL + 64;

    const int tid    = threadIdx.x;
    const int warp   = tid >> 5;
    const int lane   = tid & 31;
    const int warps  = blockDim.x >> 5;           // 24
    const int stride = gridDim.x * warps;

    const float t = __ldg(t_ptr);

    if (tid == 0) mbar_init(m_tbl, 1);

    // ---- prologue: issue DEPTH rows' index loads EARLY ----
    const int row0 = blockIdx.x * warps + warp;
    int4 buf0[4], buf1[4], buf2[4];
    #define PROLOAD(BUF, K)                                                   \
    {                                                                         \
        const int r = row0 + (K) * stride;                                    \
        if (r < B) {                                                          \
            const int4* p = reinterpret_cast<const int4*>(                    \
                idx + (size_t)r * L_SEQ);                                     \
            _Pragma("unroll")                                                 \
            for (int j = 0; j < 4; j++) BUF[j] = __ldcs(&p[j * 32 + lane]);   \
        }                                                                     \
    }
    PROLOAD(buf0, 0)
    PROLOAD(buf1, 1)
    PROLOAD(buf2, 2)
    #undef PROLOAD

    // prefetch rows DEPTH..PF_DIST-1 to L2 (lead for the first refills)
    for (int k = DEPTH; k < PF_DIST; k++) {
        const long r = (long)row0 + (long)k * stride;
        if (r < B) {
            const char* pp = reinterpret_cast<const char*>(idx + (size_t)r * L_SEQ)
                           + (lane << 6);
            asm volatile("prefetch.global.L2 [%0];" :: "l"(pp));
        }
    }

    // ---- scalar part: trapz(exp(-E),E), warps 0-3 ----
    if (tid < 128) {
        float val = 0.0f;
        if (tid < NQ - 1) {
            float Ei = ((float)tid       * (1.0f / (NQ - 1))) * t;
            float Ej = ((float)(tid + 1) * (1.0f / (NQ - 1))) * t;
            val = 0.5f * (__expf(-Ei) + __expf(-Ej)) * (Ej - Ei);
        }
        #pragma unroll
        for (int off = 16; off; off >>= 1)
            val += __shfl_xor_sync(0xffffffffu, val, off);
        if (lane == 0) ws[warp] = val;
    }
    __syncthreads();                               // mbar init + ws visible

    // ---- one bulk copy brings the whole fp16 table into smem ----
    if (tid == 0) {
        mbar_expect_tx(m_tbl, TBL);
        bulk_g2s(sbase, g_eta_h, TBL, m_tbl);
    }

    const float base = (ws[0] + ws[1] + ws[2] + ws[3])
                     - 0.5f * t * logf(t + EPSILON_F);

    mbar_wait(m_tbl, 0);                           // table ready

    // ---- desync: spread warp start phases across ~one stage period ----
    __nanosleep((unsigned)warp * 80u);

    if (row0 >= B) return;
    int row = row0;

    // stage: prefetch row+PF to L2, gather BUF's row, refill BUF (L2 hit)
    #define STAGE(BUF)                                                        \
    {                                                                         \
        const long pf = (long)row + (long)PF_DIST * stride;                   \
        if (pf < B) {                                                         \
            const char* pp = reinterpret_cast<const char*>(                   \
                idx + (size_t)pf * L_SEQ) + (lane << 6);                      \
            asm volatile("prefetch.global.L2 [%0];" :: "l"(pp));              \
        }                                                                     \
        float a = 0.0f, b = 0.0f, c = 0.0f, d = 0.0f;                         \
        _Pragma("unroll")                                                     \
        for (int j = 0; j < 4; j++) {                                         \
            a += __half2float(tbl[BUF[j].x]);                                 \
            b += __half2float(tbl[BUF[j].y]);                                 \
            c += __half2float(tbl[BUF[j].z]);                                 \
            d += __half2float(tbl[BUF[j].w]);                                 \
        }                                                                     \
        const int pre = row + DEPTH * stride;                                 \
        if (pre < B) {                                                        \
            const int4* p = reinterpret_cast<const int4*>(                    \
                idx + (size_t)pre * L_SEQ);                                   \
            _Pragma("unroll")                                                 \
            for (int j = 0; j < 4; j++) BUF[j] = __ldcs(&p[j * 32 + lane]);   \
        }                                                                     \
        float s = (a + b) + (c + d);                                          \
        _Pragma("unroll")                                                     \
        for (int off = 16; off; off >>= 1)                                    \
            s += __shfl_xor_sync(0xffffffffu, s, off);                        \
        if (lane == 0) out[row] = s + base;                                   \
    }

    for (;;) {
        STAGE(buf0); row += stride; if (row >= B) break;
        STAGE(buf1); row += stride; if (row >= B) break;
        STAGE(buf2); row += stride; if (row >= B) break;
    }
    #undef STAGE
}

extern "C" void kernel_launch(void* const* d_in, const int* in_sizes, int n_in,
                              void* d_out, int out_size) {
    const int*   idx = (const int*)d_in[0];     // [B, 512] int32
    const float* eta = (const float*)d_in[1];   // [V] f32
    const float* t   = (const float*)d_in[2];   // scalar f32
    float* out = (float*)d_out;

    const int B = in_sizes[0] / L_SEQ;
    const int V = in_sizes[1];

    // one-wave convert: ceil((V/2)/256) blocks
    const int cb = ((V >> 1) + 255) / 256;
    convert_kernel<<<cb, 256>>>(eta, V);

    int dev = 0, sms = 148;
    cudaGetDevice(&dev);
    cudaDeviceGetAttribute(&sms, cudaDevAttrMultiProcessorCount, dev);

    const size_t TBL = (size_t)((2 * V + 15) & ~15);
    const size_t smem = TBL + 64 + 64;           // table + ws + mbar
    cudaFuncSetAttribute(gather_kernel,
                         cudaFuncAttributeMaxDynamicSharedMemorySize, (int)smem);

    gather_kernel<<<sms, THREADS, smem>>>(idx, t, out, B, V);
}